// round 1
// baseline (speedup 1.0000x reference)
#include <cuda_runtime.h>
#include <cuda_bf16.h>
#include <cstdint>

#define BB 4
#define CC 256
#define NN 4096
#define DI 32
#define QSCALE 0.17677669529663687f  // 1/sqrt(32)

// Scratch (allocation-free rule: __device__ globals)
__device__ __nv_bfloat16 g_Q[BB * NN * DI];                 // [b][i][32], pre-scaled
__device__ __nv_bfloat16 g_K[BB * NN * DI];                 // [b][j][32]
__device__ __nv_bfloat16 g_V[(size_t)BB * CC * NN];         // [b][c][j]
__device__ __nv_bfloat16 g_P[(size_t)BB * NN * NN];         // [b][i][j] normalized probs

__device__ __forceinline__ void mma16816(float* c,
                                         uint32_t a0, uint32_t a1, uint32_t a2, uint32_t a3,
                                         uint32_t b0, uint32_t b1) {
    asm volatile(
        "mma.sync.aligned.m16n8k16.row.col.f32.bf16.bf16.f32 "
        "{%0,%1,%2,%3}, {%4,%5,%6,%7}, {%8,%9}, {%0,%1,%2,%3};\n"
        : "+f"(c[0]), "+f"(c[1]), "+f"(c[2]), "+f"(c[3])
        : "r"(a0), "r"(a1), "r"(a2), "r"(a3), "r"(b0), "r"(b1));
}

// ============================================================================
// Kernel 1: fused QKV projection.
// Y[o][n] = sum_c W[o][c] * x[b][c][n] + bias[o], o in [0,320)
//   o<32  -> Q[b][n][o] = (y)*QSCALE
//   o<64  -> K[b][n][o-32]
//   else  -> V[b][o-64][n]
// grid (32 ntiles of 128, 5 otiles of 64, 4 b), block 256
// ============================================================================
__global__ __launch_bounds__(256) void proj_kernel(
    const float* __restrict__ x,
    const float* __restrict__ Wq, const float* __restrict__ bq,
    const float* __restrict__ Wk, const float* __restrict__ bk,
    const float* __restrict__ Wv, const float* __restrict__ bv)
{
    __shared__ __nv_bfloat16 sA[64][40];   // weights [o][c], pad->conflict-free frags
    __shared__ __nv_bfloat16 sB[128][40];  // x^T tile [n][c]
    __shared__ float sbias[64];

    const int tid  = threadIdx.x;
    const int lane = tid & 31;
    const int warp = tid >> 5;
    const int g    = lane >> 2;
    const int tig  = lane & 3;
    const int b     = blockIdx.z;
    const int oBase = blockIdx.y * 64;
    const int n0    = blockIdx.x * 128;
    const int mBase = (warp & 3) * 16;
    const int nBase = (warp >> 2) * 64;

    if (tid < 64) {
        int oG = oBase + tid;
        float bb;
        if (oG < 32)      bb = bq[oG];
        else if (oG < 64) bb = bk[oG - 32];
        else              bb = bv[oG - 64];
        sbias[tid] = bb;
    }

    float acc[8][4];
    #pragma unroll
    for (int t = 0; t < 8; t++)
        #pragma unroll
        for (int u = 0; u < 4; u++) acc[t][u] = 0.f;

    for (int c0 = 0; c0 < CC; c0 += 32) {
        __syncthreads();
        // A tile: 64 o-rows x 32 c-cols (fp32 -> bf16)
        #pragma unroll
        for (int i = 0; i < 8; i++) {
            int idx = tid + i * 256;
            int r = idx >> 5, cc = idx & 31;
            int oG = oBase + r;
            const float* Wrow;
            if (oG < 32)      Wrow = Wq + (size_t)oG * CC;
            else if (oG < 64) Wrow = Wk + (size_t)(oG - 32) * CC;
            else              Wrow = Wv + (size_t)(oG - 64) * CC;
            sA[r][cc] = __float2bfloat16(Wrow[c0 + cc]);
        }
        // B tile: x[b][c0+cr][n0+n] -> sB[n][cr]
        #pragma unroll
        for (int i = 0; i < 4; i++) {
            int idx = tid + i * 256;
            int cr = idx >> 5;
            int nq = (idx & 31) * 4;
            const float4 v4 = *reinterpret_cast<const float4*>(
                &x[((size_t)(b * CC + c0 + cr)) * NN + n0 + nq]);
            sB[nq + 0][cr] = __float2bfloat16(v4.x);
            sB[nq + 1][cr] = __float2bfloat16(v4.y);
            sB[nq + 2][cr] = __float2bfloat16(v4.z);
            sB[nq + 3][cr] = __float2bfloat16(v4.w);
        }
        __syncthreads();
        #pragma unroll
        for (int k16 = 0; k16 < 32; k16 += 16) {
            uint32_t a0 = *(const uint32_t*)&sA[mBase + g][k16 + 2 * tig];
            uint32_t a1 = *(const uint32_t*)&sA[mBase + g + 8][k16 + 2 * tig];
            uint32_t a2 = *(const uint32_t*)&sA[mBase + g][k16 + 2 * tig + 8];
            uint32_t a3 = *(const uint32_t*)&sA[mBase + g + 8][k16 + 2 * tig + 8];
            #pragma unroll
            for (int t = 0; t < 8; t++) {
                int nr = nBase + t * 8 + g;
                uint32_t b0 = *(const uint32_t*)&sB[nr][k16 + 2 * tig];
                uint32_t b1 = *(const uint32_t*)&sB[nr][k16 + 2 * tig + 8];
                mma16816(acc[t], a0, a1, a2, a3, b0, b1);
            }
        }
    }

    // Epilogue: bias + route to Q/K/V
    #pragma unroll
    for (int t = 0; t < 8; t++) {
        int ncol = n0 + nBase + t * 8 + 2 * tig;
        #pragma unroll
        for (int half = 0; half < 2; half++) {
            int r  = mBase + g + half * 8;
            int oG = oBase + r;
            float v0 = acc[t][half * 2 + 0] + sbias[r];
            float v1 = acc[t][half * 2 + 1] + sbias[r];
            if (oG < 32) {
                v0 *= QSCALE; v1 *= QSCALE;
                g_Q[((size_t)(b * NN + ncol)) * DI + oG]     = __float2bfloat16(v0);
                g_Q[((size_t)(b * NN + ncol + 1)) * DI + oG] = __float2bfloat16(v1);
            } else if (oG < 64) {
                g_K[((size_t)(b * NN + ncol)) * DI + (oG - 32)]     = __float2bfloat16(v0);
                g_K[((size_t)(b * NN + ncol + 1)) * DI + (oG - 32)] = __float2bfloat16(v1);
            } else {
                __nv_bfloat162 p = __floats2bfloat162_rn(v0, v1);
                *reinterpret_cast<__nv_bfloat162*>(
                    &g_V[((size_t)(b * CC + (oG - 64))) * NN + ncol]) = p;
            }
        }
    }
}

// ============================================================================
// Kernel 2: scores + softmax -> P (two-pass over K, per 64-query tile)
// grid (64 itiles, 4 b), block 256
// ============================================================================
__device__ __forceinline__ void compute_stile(
    float acc[8][4],
    const __nv_bfloat16 (*sQ)[40], const __nv_bfloat16 (*sK)[40],
    int mBase, int jWBase, int g, int tig)
{
    #pragma unroll
    for (int t = 0; t < 8; t++)
        #pragma unroll
        for (int u = 0; u < 4; u++) acc[t][u] = 0.f;
    #pragma unroll
    for (int k16 = 0; k16 < 32; k16 += 16) {
        uint32_t a0 = *(const uint32_t*)&sQ[mBase + g][k16 + 2 * tig];
        uint32_t a1 = *(const uint32_t*)&sQ[mBase + g + 8][k16 + 2 * tig];
        uint32_t a2 = *(const uint32_t*)&sQ[mBase + g][k16 + 2 * tig + 8];
        uint32_t a3 = *(const uint32_t*)&sQ[mBase + g + 8][k16 + 2 * tig + 8];
        #pragma unroll
        for (int t = 0; t < 8; t++) {
            int nr = jWBase + t * 8 + g;
            uint32_t b0 = *(const uint32_t*)&sK[nr][k16 + 2 * tig];
            uint32_t b1 = *(const uint32_t*)&sK[nr][k16 + 2 * tig + 8];
            mma16816(acc[t], a0, a1, a2, a3, b0, b1);
        }
    }
}

__global__ __launch_bounds__(256) void attn_kernel()
{
    __shared__ __nv_bfloat16 sQ[64][40];
    __shared__ __nv_bfloat16 sK[128][40];
    __shared__ float sRm[2][64], sRl[2][64];
    __shared__ float sM[64], sLinv[64];

    const int tid  = threadIdx.x;
    const int lane = tid & 31;
    const int warp = tid >> 5;
    const int g    = lane >> 2;
    const int tig  = lane & 3;
    const int b  = blockIdx.y;
    const int i0 = blockIdx.x * 64;
    const int mBase  = (warp & 3) * 16;
    const int wn     = warp >> 2;
    const int jWBase = wn * 64;

    // Q tile (stays resident)
    {
        int r = tid >> 2, c8 = (tid & 3) * 8;
        *reinterpret_cast<uint4*>(&sQ[r][c8]) =
            *reinterpret_cast<const uint4*>(&g_Q[((size_t)(b * NN + i0 + r)) * DI + c8]);
    }

    // ---- Pass A: row max + sum of exp ----
    float rmax[2] = {-1e30f, -1e30f};
    float rsum[2] = {0.f, 0.f};
    for (int jt = 0; jt < NN; jt += 128) {
        __syncthreads();
        #pragma unroll
        for (int i = 0; i < 2; i++) {
            int idx = tid + i * 256;
            int r = idx >> 2, c8 = (idx & 3) * 8;
            *reinterpret_cast<uint4*>(&sK[r][c8]) =
                *reinterpret_cast<const uint4*>(&g_K[((size_t)(b * NN + jt + r)) * DI + c8]);
        }
        __syncthreads();
        float acc[8][4];
        compute_stile(acc, sQ, sK, mBase, jWBase, g, tig);
        #pragma unroll
        for (int half = 0; half < 2; half++) {
            float tmax = -1e30f;
            #pragma unroll
            for (int t = 0; t < 8; t++) {
                tmax = fmaxf(tmax, acc[t][half * 2 + 0]);
                tmax = fmaxf(tmax, acc[t][half * 2 + 1]);
            }
            float nm = fmaxf(rmax[half], tmax);
            float s = rsum[half] * __expf(rmax[half] - nm);
            #pragma unroll
            for (int t = 0; t < 8; t++) {
                s += __expf(acc[t][half * 2 + 0] - nm);
                s += __expf(acc[t][half * 2 + 1] - nm);
            }
            rsum[half] = s;
            rmax[half] = nm;
        }
    }
    // reduce across tig (4 lanes share a row)
    #pragma unroll
    for (int half = 0; half < 2; half++) {
        float m = rmax[half], l = rsum[half];
        #pragma unroll
        for (int off = 1; off < 4; off <<= 1) {
            float om = __shfl_xor_sync(0xffffffffu, m, off);
            float ol = __shfl_xor_sync(0xffffffffu, l, off);
            float nm = fmaxf(m, om);
            l = l * __expf(m - nm) + ol * __expf(om - nm);
            m = nm;
        }
        rmax[half] = m; rsum[half] = l;
    }
    if (tig == 0) {
        sRm[wn][mBase + g]     = rmax[0]; sRl[wn][mBase + g]     = rsum[0];
        sRm[wn][mBase + g + 8] = rmax[1]; sRl[wn][mBase + g + 8] = rsum[1];
    }
    __syncthreads();
    if (tid < 64) {
        float m0 = sRm[0][tid], l0 = sRl[0][tid];
        float m1 = sRm[1][tid], l1 = sRl[1][tid];
        float nm = fmaxf(m0, m1);
        float l  = l0 * __expf(m0 - nm) + l1 * __expf(m1 - nm);
        sM[tid] = nm; sLinv[tid] = 1.f / l;
    }
    __syncthreads();
    const float M0  = sM[mBase + g],     Li0 = sLinv[mBase + g];
    const float M1  = sM[mBase + g + 8], Li1 = sLinv[mBase + g + 8];

    // ---- Pass B: recompute, normalize, store P (bf16) ----
    for (int jt = 0; jt < NN; jt += 128) {
        __syncthreads();
        #pragma unroll
        for (int i = 0; i < 2; i++) {
            int idx = tid + i * 256;
            int r = idx >> 2, c8 = (idx & 3) * 8;
            *reinterpret_cast<uint4*>(&sK[r][c8]) =
                *reinterpret_cast<const uint4*>(&g_K[((size_t)(b * NN + jt + r)) * DI + c8]);
        }
        __syncthreads();
        float acc[8][4];
        compute_stile(acc, sQ, sK, mBase, jWBase, g, tig);
        #pragma unroll
        for (int t = 0; t < 8; t++) {
            int j = jt + jWBase + t * 8 + 2 * tig;
            float p00 = __expf(acc[t][0] - M0) * Li0;
            float p01 = __expf(acc[t][1] - M0) * Li0;
            float p10 = __expf(acc[t][2] - M1) * Li1;
            float p11 = __expf(acc[t][3] - M1) * Li1;
            *reinterpret_cast<__nv_bfloat162*>(
                &g_P[((size_t)(b * NN + i0 + mBase + g)) * NN + j]) =
                __floats2bfloat162_rn(p00, p01);
            *reinterpret_cast<__nv_bfloat162*>(
                &g_P[((size_t)(b * NN + i0 + mBase + g + 8)) * NN + j]) =
                __floats2bfloat162_rn(p10, p11);
        }
    }
}

// ============================================================================
// Kernel 3: out[b][c][i] = gamma * sum_j V[c][j]*P[i][j] + x[b][c][i]
// grid (32 itiles of 128, 2 ctiles of 128, 4 b), block 256
// ============================================================================
__global__ __launch_bounds__(256) void pv_kernel(
    const float* __restrict__ x, const float* __restrict__ gamma,
    float* __restrict__ out)
{
    __shared__ __nv_bfloat16 sV[128][72];  // [c][j]
    __shared__ __nv_bfloat16 sP[128][72];  // [i][j]

    const int tid  = threadIdx.x;
    const int lane = tid & 31;
    const int warp = tid >> 5;
    const int g    = lane >> 2;
    const int tig  = lane & 3;
    const int b     = blockIdx.z;
    const int cBase = blockIdx.y * 128;
    const int iBase = blockIdx.x * 128;
    const int wm = (warp & 1) * 64;   // 4 m-subtiles of 16
    const int wn = (warp >> 1) * 32;  // 4 n-subtiles of 8

    float acc[4][4][4];
    #pragma unroll
    for (int ms = 0; ms < 4; ms++)
        #pragma unroll
        for (int ns = 0; ns < 4; ns++)
            #pragma unroll
            for (int u = 0; u < 4; u++) acc[ms][ns][u] = 0.f;

    for (int j0 = 0; j0 < NN; j0 += 64) {
        __syncthreads();
        #pragma unroll
        for (int i = 0; i < 4; i++) {
            int idx = tid + i * 256;
            int r = idx >> 3, c8 = (idx & 7) * 8;
            *reinterpret_cast<uint4*>(&sV[r][c8]) =
                *reinterpret_cast<const uint4*>(
                    &g_V[((size_t)(b * CC + cBase + r)) * NN + j0 + c8]);
            *reinterpret_cast<uint4*>(&sP[r][c8]) =
                *reinterpret_cast<const uint4*>(
                    &g_P[((size_t)(b * NN + iBase + r)) * NN + j0 + c8]);
        }
        __syncthreads();
        #pragma unroll
        for (int k16 = 0; k16 < 64; k16 += 16) {
            uint32_t af[4][4];
            #pragma unroll
            for (int ms = 0; ms < 4; ms++) {
                int row = wm + ms * 16 + g;
                af[ms][0] = *(const uint32_t*)&sV[row][k16 + 2 * tig];
                af[ms][1] = *(const uint32_t*)&sV[row + 8][k16 + 2 * tig];
                af[ms][2] = *(const uint32_t*)&sV[row][k16 + 2 * tig + 8];
                af[ms][3] = *(const uint32_t*)&sV[row + 8][k16 + 2 * tig + 8];
            }
            #pragma unroll
            for (int ns = 0; ns < 4; ns++) {
                int nr = wn + ns * 8 + g;
                uint32_t b0 = *(const uint32_t*)&sP[nr][k16 + 2 * tig];
                uint32_t b1 = *(const uint32_t*)&sP[nr][k16 + 2 * tig + 8];
                #pragma unroll
                for (int ms = 0; ms < 4; ms++)
                    mma16816(acc[ms][ns], af[ms][0], af[ms][1], af[ms][2], af[ms][3], b0, b1);
            }
        }
    }

    const float gm = __ldg(gamma);
    #pragma unroll
    for (int ms = 0; ms < 4; ms++) {
        #pragma unroll
        for (int ns = 0; ns < 4; ns++) {
            int icol = iBase + wn + ns * 8 + 2 * tig;
            #pragma unroll
            for (int half = 0; half < 2; half++) {
                int crow = cBase + wm + ms * 16 + g + half * 8;
                size_t base = ((size_t)(b * CC + crow)) * NN + icol;
                float2 xv = *reinterpret_cast<const float2*>(&x[base]);
                float2 ov;
                ov.x = gm * acc[ms][ns][half * 2 + 0] + xv.x;
                ov.y = gm * acc[ms][ns][half * 2 + 1] + xv.y;
                *reinterpret_cast<float2*>(&out[base]) = ov;
            }
        }
    }
}

// ============================================================================
extern "C" void kernel_launch(void* const* d_in, const int* in_sizes, int n_in,
                              void* d_out, int out_size)
{
    const float* x     = (const float*)d_in[0];
    const float* Wq    = (const float*)d_in[1];
    const float* bq    = (const float*)d_in[2];
    const float* Wk    = (const float*)d_in[3];
    const float* bk    = (const float*)d_in[4];
    const float* Wv    = (const float*)d_in[5];
    const float* bv    = (const float*)d_in[6];
    const float* gamma = (const float*)d_in[7];
    float* out = (float*)d_out;

    proj_kernel<<<dim3(32, 5, 4), 256>>>(x, Wq, bq, Wk, bk, Wv, bv);
    attn_kernel<<<dim3(64, 4), 256>>>();
    pv_kernel<<<dim3(32, 2, 4), 256>>>(x, gamma, out);
}

// round 11
// speedup vs baseline: 1.0230x; 1.0230x over previous
#include <cuda_runtime.h>
#include <cuda_bf16.h>
#include <cstdint>

#define BB 4
#define CC 256
#define NN 4096
#define DI 32
#define QSCALE 0.17677669529663687f  // 1/sqrt(32)

// Scratch (allocation-free rule: __device__ globals)
__device__ __nv_bfloat16 g_Q[BB * NN * DI];          // [b][i][32], pre-scaled
__device__ __nv_bfloat16 g_K[BB * NN * DI];          // [b][j][32]
__device__ __nv_bfloat16 g_V[(size_t)BB * CC * NN];  // [b][c][j]

__device__ __forceinline__ void mma16816(float* c,
                                         uint32_t a0, uint32_t a1, uint32_t a2, uint32_t a3,
                                         uint32_t b0, uint32_t b1) {
    asm volatile(
        "mma.sync.aligned.m16n8k16.row.col.f32.bf16.bf16.f32 "
        "{%0,%1,%2,%3}, {%4,%5,%6,%7}, {%8,%9}, {%0,%1,%2,%3};\n"
        : "+f"(c[0]), "+f"(c[1]), "+f"(c[2]), "+f"(c[3])
        : "r"(a0), "r"(a1), "r"(a2), "r"(a3), "r"(b0), "r"(b1));
}

__device__ __forceinline__ void ldsm_x4_t(uint32_t& r0, uint32_t& r1,
                                          uint32_t& r2, uint32_t& r3, uint32_t addr) {
    asm volatile(
        "ldmatrix.sync.aligned.m8n8.x4.trans.shared.b16 {%0,%1,%2,%3}, [%4];\n"
        : "=r"(r0), "=r"(r1), "=r"(r2), "=r"(r3) : "r"(addr));
}

// ============================================================================
// Kernel 1: fused QKV projection, x staged once per CTA.
// grid (64 ntiles of 64, 4 b), block 256.
// smem: sX[256 c][72] bf16 (x tile, natural layout), sW[64 o][264] bf16.
// B-fragments (n,k) obtained via ldmatrix.x4.trans on sX.
// ============================================================================
#define PROJ_SMEM (256 * 72 * 2 + 64 * 264 * 2 + 256)

__global__ __launch_bounds__(256) void proj_kernel(
    const float* __restrict__ x,
    const float* __restrict__ Wq, const float* __restrict__ bq,
    const float* __restrict__ Wk, const float* __restrict__ bk,
    const float* __restrict__ Wv, const float* __restrict__ bv)
{
    extern __shared__ char sm[];
    __nv_bfloat16 (*sX)[72]  = reinterpret_cast<__nv_bfloat16(*)[72]>(sm);
    __nv_bfloat16 (*sW)[264] = reinterpret_cast<__nv_bfloat16(*)[264]>(sm + 256 * 72 * 2);
    float* sbias = reinterpret_cast<float*>(sm + 256 * 72 * 2 + 64 * 264 * 2);

    const int tid  = threadIdx.x;
    const int lane = tid & 31;
    const int warp = tid >> 5;
    const int g    = lane >> 2;
    const int tig  = lane & 3;
    const int b  = blockIdx.y;
    const int n0 = blockIdx.x * 64;
    const int mBase = (warp & 3) * 16;   // o rows within chunk
    const int nW    = (warp >> 2) * 32;  // n cols within tile

    // Stage x tile [256 c][64 n] fp32 -> bf16 (read from DRAM exactly once)
    #pragma unroll
    for (int it = 0; it < 16; it++) {
        int idx = tid + it * 256;
        int r = idx >> 4, cq = (idx & 15) * 4;
        const float4 v = *reinterpret_cast<const float4*>(
            &x[((size_t)(b * CC + r)) * NN + n0 + cq]);
        __nv_bfloat162* d = reinterpret_cast<__nv_bfloat162*>(&sX[r][cq]);
        d[0] = __floats2bfloat162_rn(v.x, v.y);
        d[1] = __floats2bfloat162_rn(v.z, v.w);
    }

    // precompute ldmatrix row address offsets (lane-dependent)
    const int lrow = ((lane >> 3) & 1) * 8 + (lane & 7);  // row within k16 block
    const int lcol = (lane >> 4) * 8;                     // n-block select

    for (int oc = 0; oc < 5; oc++) {
        __syncthreads();  // protects sX (first iter) / sW+sbias reuse (later)
        // Load W chunk: rows [oc*64, oc*64+64) x 256 c
        #pragma unroll
        for (int it = 0; it < 16; it++) {
            int idx = tid + it * 256;
            int r = idx >> 6, c4 = (idx & 63) * 4;
            int oG = oc * 64 + r;
            const float* Wrow;
            if (oG < 32)      Wrow = Wq + (size_t)oG * CC;
            else if (oG < 64) Wrow = Wk + (size_t)(oG - 32) * CC;
            else              Wrow = Wv + (size_t)(oG - 64) * CC;
            const float4 v = *reinterpret_cast<const float4*>(&Wrow[c4]);
            __nv_bfloat162* d = reinterpret_cast<__nv_bfloat162*>(&sW[r][c4]);
            d[0] = __floats2bfloat162_rn(v.x, v.y);
            d[1] = __floats2bfloat162_rn(v.z, v.w);
        }
        if (tid < 64) {
            int oG = oc * 64 + tid;
            float bb;
            if (oG < 32)      bb = bq[oG];
            else if (oG < 64) bb = bk[oG - 32];
            else              bb = bv[oG - 64];
            sbias[tid] = bb;
        }
        __syncthreads();

        float acc[4][4];
        #pragma unroll
        for (int ns = 0; ns < 4; ns++)
            #pragma unroll
            for (int u = 0; u < 4; u++) acc[ns][u] = 0.f;

        #pragma unroll
        for (int k = 0; k < 256; k += 16) {
            uint32_t a0 = *(const uint32_t*)&sW[mBase + g][k + 2 * tig];
            uint32_t a1 = *(const uint32_t*)&sW[mBase + g + 8][k + 2 * tig];
            uint32_t a2 = *(const uint32_t*)&sW[mBase + g][k + 2 * tig + 8];
            uint32_t a3 = *(const uint32_t*)&sW[mBase + g + 8][k + 2 * tig + 8];
            uint32_t b00, b01, b10, b11, b20, b21, b30, b31;
            uint32_t ad0 = (uint32_t)__cvta_generic_to_shared(&sX[k + lrow][nW + lcol]);
            ldsm_x4_t(b00, b01, b10, b11, ad0);   // ns0: {b00,b01}, ns1: {b10,b11}
            uint32_t ad1 = (uint32_t)__cvta_generic_to_shared(&sX[k + lrow][nW + 16 + lcol]);
            ldsm_x4_t(b20, b21, b30, b31, ad1);   // ns2, ns3
            mma16816(acc[0], a0, a1, a2, a3, b00, b01);
            mma16816(acc[1], a0, a1, a2, a3, b10, b11);
            mma16816(acc[2], a0, a1, a2, a3, b20, b21);
            mma16816(acc[3], a0, a1, a2, a3, b30, b31);
        }

        // Epilogue: bias + route o-chunk to Q/K/V
        #pragma unroll
        for (int ns = 0; ns < 4; ns++) {
            int ncol = n0 + nW + ns * 8 + 2 * tig;
            #pragma unroll
            for (int half = 0; half < 2; half++) {
                int r  = mBase + g + half * 8;
                int oG = oc * 64 + r;
                float v0 = acc[ns][half * 2 + 0] + sbias[r];
                float v1 = acc[ns][half * 2 + 1] + sbias[r];
                if (oG < 32) {
                    v0 *= QSCALE; v1 *= QSCALE;
                    g_Q[((size_t)(b * NN + ncol)) * DI + oG]     = __float2bfloat16(v0);
                    g_Q[((size_t)(b * NN + ncol + 1)) * DI + oG] = __float2bfloat16(v1);
                } else if (oG < 64) {
                    g_K[((size_t)(b * NN + ncol)) * DI + (oG - 32)]     = __float2bfloat16(v0);
                    g_K[((size_t)(b * NN + ncol + 1)) * DI + (oG - 32)] = __float2bfloat16(v1);
                } else {
                    *reinterpret_cast<__nv_bfloat162*>(
                        &g_V[((size_t)(b * CC + (oG - 64))) * NN + ncol]) =
                        __floats2bfloat162_rn(v0, v1);
                }
            }
        }
    }
}

// ============================================================================
// Kernel 2: fused flash attention + PV + epilogue. No P in global memory.
// grid (64 itiles of 64, 4 b), block 256 (8 warps).
//   warps 0-3: S = Q K^T (16 i-rows each, full 64 j), online softmax,
//              write unnormalized P tile to smem, per-row rescale factor.
//   warps 4-7: load V tile concurrently.
//   all warps: O accumulation (warp tile: 64 c x 32 i), final epilogue.
// ============================================================================
#define FL_SV_OFF   0
#define FL_SK_OFF   (256 * 72 * 2)                    // 36864
#define FL_SP_OFF   (FL_SK_OFF + 64 * 40 * 2)         // 41984
#define FL_FAC_OFF  (FL_SP_OFF + 64 * 72 * 2)         // 51200
#define FL_LINV_OFF (FL_FAC_OFF + 64 * 4)             // 51456
#define FLASH_SMEM  (FL_LINV_OFF + 64 * 4)            // 51712

__global__ __launch_bounds__(256) void flash_kernel(
    const float* __restrict__ x, const float* __restrict__ gamma,
    float* __restrict__ out)
{
    extern __shared__ char sm[];
    __nv_bfloat16 (*sV)[72] = reinterpret_cast<__nv_bfloat16(*)[72]>(sm + FL_SV_OFF);
    __nv_bfloat16 (*sK)[40] = reinterpret_cast<__nv_bfloat16(*)[40]>(sm + FL_SK_OFF);
    __nv_bfloat16 (*sP)[72] = reinterpret_cast<__nv_bfloat16(*)[72]>(sm + FL_SP_OFF);
    float* sFac  = reinterpret_cast<float*>(sm + FL_FAC_OFF);
    float* sLinv = reinterpret_cast<float*>(sm + FL_LINV_OFF);

    const int tid  = threadIdx.x;
    const int lane = tid & 31;
    const int warp = tid >> 5;
    const int g    = lane >> 2;
    const int tig  = lane & 3;
    const int b  = blockIdx.y;
    const int i0 = blockIdx.x * 64;
    const int wc = warp & 3;   // c chunk (64 wide)
    const int wi = warp >> 2;  // i chunk (32 wide)
    const bool isS = (warp < 4);

    float acc[4][4][4];
    #pragma unroll
    for (int ms = 0; ms < 4; ms++)
        #pragma unroll
        for (int ns = 0; ns < 4; ns++)
            #pragma unroll
            for (int u = 0; u < 4; u++) acc[ms][ns][u] = 0.f;

    // S-warp state: Q fragments pinned in registers, online softmax stats
    uint32_t aQ[2][4];
    float m_run[2] = {-1e30f, -1e30f};
    float l_run[2] = {0.f, 0.f};
    if (isS) {
        size_t rowg = (size_t)(b * NN + i0 + warp * 16 + g);
        #pragma unroll
        for (int k = 0; k < 2; k++) {
            aQ[k][0] = *(const uint32_t*)&g_Q[rowg * DI + k * 16 + 2 * tig];
            aQ[k][1] = *(const uint32_t*)&g_Q[(rowg + 8) * DI + k * 16 + 2 * tig];
            aQ[k][2] = *(const uint32_t*)&g_Q[rowg * DI + k * 16 + 2 * tig + 8];
            aQ[k][3] = *(const uint32_t*)&g_Q[(rowg + 8) * DI + k * 16 + 2 * tig + 8];
        }
    }

    for (int j0 = 0; j0 < NN; j0 += 64) {
        __syncthreads();  // prev PV done reading sP/sV; safe to overwrite tiles
        if (tid < 128) {
            // K tile [64 j][32] (loaded by the S warps themselves)
            #pragma unroll
            for (int it = 0; it < 2; it++) {
                int idx = tid + it * 128;
                int r = idx >> 2, c8 = (idx & 3) * 8;
                *reinterpret_cast<uint4*>(&sK[r][c8]) =
                    *reinterpret_cast<const uint4*>(
                        &g_K[((size_t)(b * NN + j0 + r)) * DI + c8]);
            }
        } else {
            // V tile [256 c][64 j] (warps 4-7, overlapped with S compute)
            #pragma unroll
            for (int it = 0; it < 16; it++) {
                int idx = (tid - 128) + it * 128;
                int r = idx >> 3, c8 = (idx & 7) * 8;
                *reinterpret_cast<uint4*>(&sV[r][c8]) =
                    *reinterpret_cast<const uint4*>(
                        &g_V[((size_t)(b * CC + r)) * NN + j0 + c8]);
            }
        }

        if (isS) {
            asm volatile("bar.sync 1, 128;" ::: "memory");  // K tile ready (warps 0-3)
            float accS[8][4];
            #pragma unroll
            for (int ns = 0; ns < 8; ns++)
                #pragma unroll
                for (int u = 0; u < 4; u++) accS[ns][u] = 0.f;
            #pragma unroll
            for (int k = 0; k < 2; k++) {
                #pragma unroll
                for (int ns = 0; ns < 8; ns++) {
                    uint32_t b0 = *(const uint32_t*)&sK[ns * 8 + g][k * 16 + 2 * tig];
                    uint32_t b1 = *(const uint32_t*)&sK[ns * 8 + g][k * 16 + 2 * tig + 8];
                    mma16816(accS[ns], aQ[k][0], aQ[k][1], aQ[k][2], aQ[k][3], b0, b1);
                }
            }
            // online softmax per row (rows g and g+8 of this warp's 16-row block)
            #pragma unroll
            for (int half = 0; half < 2; half++) {
                float tmax = -1e30f;
                #pragma unroll
                for (int ns = 0; ns < 8; ns++) {
                    tmax = fmaxf(tmax, accS[ns][half * 2 + 0]);
                    tmax = fmaxf(tmax, accS[ns][half * 2 + 1]);
                }
                tmax = fmaxf(tmax, __shfl_xor_sync(0xffffffffu, tmax, 1));
                tmax = fmaxf(tmax, __shfl_xor_sync(0xffffffffu, tmax, 2));
                float mn  = fmaxf(m_run[half], tmax);
                float fac = __expf(m_run[half] - mn);
                int irow = warp * 16 + g + half * 8;
                float s = 0.f;
                #pragma unroll
                for (int ns = 0; ns < 8; ns++) {
                    float p0 = __expf(accS[ns][half * 2 + 0] - mn);
                    float p1 = __expf(accS[ns][half * 2 + 1] - mn);
                    s += p0 + p1;
                    *reinterpret_cast<__nv_bfloat162*>(&sP[irow][ns * 8 + 2 * tig]) =
                        __floats2bfloat162_rn(p0, p1);
                }
                s += __shfl_xor_sync(0xffffffffu, s, 1);
                s += __shfl_xor_sync(0xffffffffu, s, 2);
                l_run[half] = l_run[half] * fac + s;
                m_run[half] = mn;
                if (tig == 0) sFac[irow] = fac;
            }
        }
        __syncthreads();  // P tile + factors + V tile ready

        // ---- PV accumulation (all 8 warps) ----
        #pragma unroll
        for (int ns = 0; ns < 4; ns++) {
            int iv = wi * 32 + ns * 8 + 2 * tig;
            float f0 = sFac[iv], f1 = sFac[iv + 1];
            #pragma unroll
            for (int ms = 0; ms < 4; ms++) {
                acc[ms][ns][0] *= f0; acc[ms][ns][1] *= f1;
                acc[ms][ns][2] *= f0; acc[ms][ns][3] *= f1;
            }
        }
        #pragma unroll
        for (int k = 0; k < 4; k++) {
            uint32_t av[4][4];
            #pragma unroll
            for (int ms = 0; ms < 4; ms++) {
                int row = wc * 64 + ms * 16 + g;
                av[ms][0] = *(const uint32_t*)&sV[row][k * 16 + 2 * tig];
                av[ms][1] = *(const uint32_t*)&sV[row + 8][k * 16 + 2 * tig];
                av[ms][2] = *(const uint32_t*)&sV[row][k * 16 + 2 * tig + 8];
                av[ms][3] = *(const uint32_t*)&sV[row + 8][k * 16 + 2 * tig + 8];
            }
            uint32_t bp[4][2];
            #pragma unroll
            for (int ns = 0; ns < 4; ns++) {
                int r = wi * 32 + ns * 8 + g;
                bp[ns][0] = *(const uint32_t*)&sP[r][k * 16 + 2 * tig];
                bp[ns][1] = *(const uint32_t*)&sP[r][k * 16 + 2 * tig + 8];
            }
            #pragma unroll
            for (int ms = 0; ms < 4; ms++)
                #pragma unroll
                for (int ns = 0; ns < 4; ns++)
                    mma16816(acc[ms][ns], av[ms][0], av[ms][1], av[ms][2], av[ms][3],
                             bp[ns][0], bp[ns][1]);
        }
    }

    // final 1/l
    if (isS && tig == 0) {
        sLinv[warp * 16 + g]     = 1.f / l_run[0];
        sLinv[warp * 16 + g + 8] = 1.f / l_run[1];
    }
    __syncthreads();

    const float gm = __ldg(gamma);
    #pragma unroll
    for (int ns = 0; ns < 4; ns++) {
        int iloc = wi * 32 + ns * 8 + 2 * tig;
        int iv   = i0 + iloc;
        float li0 = sLinv[iloc], li1 = sLinv[iloc + 1];
        #pragma unroll
        for (int ms = 0; ms < 4; ms++) {
            #pragma unroll
            for (int half = 0; half < 2; half++) {
                int c = wc * 64 + ms * 16 + g + half * 8;
                size_t base = ((size_t)(b * CC + c)) * NN + iv;
                float2 xv = *reinterpret_cast<const float2*>(&x[base]);
                float2 ov;
                ov.x = gm * acc[ms][ns][half * 2 + 0] * li0 + xv.x;
                ov.y = gm * acc[ms][ns][half * 2 + 1] * li1 + xv.y;
                *reinterpret_cast<float2*>(&out[base]) = ov;
            }
        }
    }
}

// ============================================================================
extern "C" void kernel_launch(void* const* d_in, const int* in_sizes, int n_in,
                              void* d_out, int out_size)
{
    const float* x     = (const float*)d_in[0];
    const float* Wq    = (const float*)d_in[1];
    const float* bq    = (const float*)d_in[2];
    const float* Wk    = (const float*)d_in[3];
    const float* bk    = (const float*)d_in[4];
    const float* Wv    = (const float*)d_in[5];
    const float* bv    = (const float*)d_in[6];
    const float* gamma = (const float*)d_in[7];
    float* out = (float*)d_out;

    cudaFuncSetAttribute(proj_kernel,  cudaFuncAttributeMaxDynamicSharedMemorySize, PROJ_SMEM);
    cudaFuncSetAttribute(flash_kernel, cudaFuncAttributeMaxDynamicSharedMemorySize, FLASH_SMEM);

    proj_kernel<<<dim3(64, 4), 256, PROJ_SMEM>>>(x, Wq, bq, Wk, bk, Wv, bv);
    flash_kernel<<<dim3(64, 4), 256, FLASH_SMEM>>>(x, gamma, out);
}